// round 6
// baseline (speedup 1.0000x reference)
#include <cuda_runtime.h>
#include <math.h>
#include <stdint.h>

#define HH 8
#define HD 32
#define BB 4
#define NN 2048
#define DD 256
#define BH (BB*HH)   // 32

// ---- device scratch (static: allocation-free rule) ----
__device__ float g_Q[(size_t)BH*NN*HD];
__device__ float g_K[(size_t)BH*NN*HD];
__device__ uint32_t g_P[(size_t)BH*NN*NN/2];   // bf16 pairs, 256 MB
__device__ float g_rowsum[BH*NN];
__device__ float g_t0[(size_t)BH*NN*HD];
__device__ float g_t1[(size_t)BH*NN*HD];
__device__ float g_acc[(size_t)BH*NN*HD];

__device__ __forceinline__ uint32_t f2tf(float f) {
    uint32_t r;
    asm("cvt.rna.tf32.f32 %0, %1;" : "=r"(r) : "f"(f));
    return r;
}

// pack two fp32 -> bf16x2 (lo in low half, hi in high half)
__device__ __forceinline__ uint32_t pack_bf16(float lo, float hi) {
    uint32_t r;
    asm("cvt.rn.bf16x2.f32 %0, %1, %2;" : "=r"(r) : "f"(hi), "f"(lo));
    return r;
}

__device__ __forceinline__ void mma_tf32(float& d0, float& d1, float& d2, float& d3,
                                         uint32_t a0, uint32_t a1, uint32_t a2, uint32_t a3,
                                         uint32_t b0, uint32_t b1) {
    asm("mma.sync.aligned.m16n8k8.row.col.f32.tf32.tf32.f32 "
        "{%0,%1,%2,%3},{%4,%5,%6,%7},{%8,%9},{%0,%1,%2,%3};"
        : "+f"(d0), "+f"(d1), "+f"(d2), "+f"(d3)
        : "r"(a0), "r"(a1), "r"(a2), "r"(a3), "r"(b0), "r"(b1));
}

__device__ __forceinline__ void mma_bf16(float& d0, float& d1, float& d2, float& d3,
                                         uint32_t a0, uint32_t a1, uint32_t a2, uint32_t a3,
                                         uint32_t b0, uint32_t b1) {
    asm("mma.sync.aligned.m16n8k16.row.col.f32.bf16.bf16.f32 "
        "{%0,%1,%2,%3},{%4,%5,%6,%7},{%8,%9},{%0,%1,%2,%3};"
        : "+f"(d0), "+f"(d1), "+f"(d2), "+f"(d3)
        : "r"(a0), "r"(a1), "r"(a2), "r"(a3), "r"(b0), "r"(b1));
}

__device__ __forceinline__ void cp16(uint32_t saddr, const void* gptr) {
    asm volatile("cp.async.cg.shared.global [%0], [%1], 16;" :: "r"(saddr), "l"(gptr));
}

// ============================================================
// Kernel 1: QKV projection + head split. (scalar fp32 — small)
// ============================================================
__global__ void qkv_kernel(const float* __restrict__ x,
                           const float* __restrict__ Wq, const float* __restrict__ bq,
                           const float* __restrict__ Wk, const float* __restrict__ bk,
                           const float* __restrict__ Wv, const float* __restrict__ bv,
                           const float* __restrict__ coeffs) {
    const int mat = blockIdx.z;
    const float* W    = (mat == 0) ? Wq : ((mat == 1) ? Wk : Wv);
    const float* bias = (mat == 0) ? bq : ((mat == 1) ? bk : bv);
    const int m0 = blockIdx.x * 64;
    const int c0 = blockIdx.y * 64;

    __shared__ float Xs[64][33];
    __shared__ float Ws[32][64];

    const int tid = threadIdx.x;
    const int ty = tid >> 4, tx = tid & 15;

    float acc[4][4] = {};

    for (int k0 = 0; k0 < DD; k0 += 32) {
        for (int l = tid; l < 512; l += 256) {
            int r = l >> 3, kq = l & 7;
            float4 v = *(const float4*)(x + (size_t)(m0 + r) * DD + k0 + kq * 4);
            Xs[r][kq*4+0] = v.x; Xs[r][kq*4+1] = v.y;
            Xs[r][kq*4+2] = v.z; Xs[r][kq*4+3] = v.w;
        }
        for (int l = tid; l < 512; l += 256) {
            int k = l >> 4, cq = l & 15;
            *(float4*)&Ws[k][cq*4] = *(const float4*)(W + (size_t)(k0 + k) * DD + c0 + cq * 4);
        }
        __syncthreads();
        #pragma unroll
        for (int kk = 0; kk < 32; kk++) {
            float a0 = Xs[ty*4+0][kk];
            float a1 = Xs[ty*4+1][kk];
            float a2 = Xs[ty*4+2][kk];
            float a3 = Xs[ty*4+3][kk];
            float4 b = *(float4*)&Ws[kk][tx*4];
            acc[0][0] += a0*b.x; acc[0][1] += a0*b.y; acc[0][2] += a0*b.z; acc[0][3] += a0*b.w;
            acc[1][0] += a1*b.x; acc[1][1] += a1*b.y; acc[1][2] += a1*b.z; acc[1][3] += a1*b.w;
            acc[2][0] += a2*b.x; acc[2][1] += a2*b.y; acc[2][2] += a2*b.z; acc[2][3] += a2*b.w;
            acc[3][0] += a3*b.x; acc[3][1] += a3*b.y; acc[3][2] += a3*b.z; acc[3][3] += a3*b.w;
        }
        __syncthreads();
    }

    #pragma unroll
    for (int i = 0; i < 4; i++) {
        int m = m0 + ty * 4 + i;
        int b_ = m >> 11, n = m & 2047;
        #pragma unroll
        for (int j = 0; j < 4; j++) {
            int c = c0 + tx * 4 + j;
            float val = acc[i][j] + bias[c];
            int h = c >> 5, d = c & 31;
            size_t idx = ((size_t)(b_ * HH + h) * NN + n) * HD + d;
            if (mat == 0)      g_Q[idx] = val;
            else if (mat == 1) g_K[idx] = val;
            else {
                g_t0[idx]  = val;
                g_acc[idx] = coeffs[h * 4] * val;   // c0 * v
            }
        }
    }
}

// ============================================================
// Kernel 2: attnP + fused pass 1 (flash-style).
//   P = exp(QK^T*scale) stored bf16; rowsums; y = P*v accumulated,
//   then t1 = y/rowsum, g_acc += c1*t1.
// grid (16 row-tiles of 128, 32 bh), block 256 (8 warps).
// ============================================================
__global__ void attnP_kernel(const float* __restrict__ coeffs) {
    const int bh = blockIdx.y;
    const int r0 = blockIdx.x * 128;
    const float c1 = coeffs[(bh & 7) * 4 + 1];

    __shared__ uint32_t Qs[128][36];   // tf32 bits
    __shared__ uint32_t Ks[128][36];
    __shared__ uint32_t Vs[64][40];    // bf16 row-pairs of v tile

    const int tid  = threadIdx.x;
    const int warp = tid >> 5;
    const int lane = tid & 31;
    const int g  = lane >> 2;   // 0..7
    const int qd = lane & 3;    // 0..3

    const float scale = 0.17677669529663687f;  // 1/sqrt(32), folded into Q

    const float* Qb = g_Q + ((size_t)bh * NN + r0) * HD;
    for (int l = tid; l < 1024; l += 256) {
        int r = l >> 3, kq = l & 7;
        float4 v = *(const float4*)(Qb + (size_t)r * HD + kq * 4);
        uint4 u;
        u.x = f2tf(v.x * scale); u.y = f2tf(v.y * scale);
        u.z = f2tf(v.z * scale); u.w = f2tf(v.w * scale);
        *(uint4*)&Qs[r][kq*4] = u;
    }
    __syncthreads();

    const int row_l = warp * 16 + g;
    float rs_lo = 0.f, rs_hi = 0.f;
    float accy[4][4];                         // y = P*v accumulator (unnormalized)
    #pragma unroll
    for (int j = 0; j < 4; j++) {
        accy[j][0]=0.f; accy[j][1]=0.f; accy[j][2]=0.f; accy[j][3]=0.f;
    }

    const float* Vb = g_t0 + (size_t)bh * NN * HD;

    for (int ct = 0; ct < 16; ct++) {
        const int c0 = ct * 128;
        const float* Kb = g_K + ((size_t)bh * NN + c0) * HD;
        for (int l = tid; l < 1024; l += 256) {
            int r = l >> 3, kq = l & 7;
            float4 v = *(const float4*)(Kb + (size_t)r * HD + kq * 4);
            uint4 u;
            u.x = f2tf(v.x); u.y = f2tf(v.y);
            u.z = f2tf(v.z); u.w = f2tf(v.w);
            *(uint4*)&Ks[r][kq*4] = u;
        }
        // stage v rows [c0, c0+128) as bf16 row-pairs
        for (int l = tid; l < 512; l += 256) {
            int m2 = l >> 3, cq = l & 7;
            float4 v0 = *(const float4*)(Vb + (size_t)(c0 + 2*m2    ) * HD + cq * 4);
            float4 v1 = *(const float4*)(Vb + (size_t)(c0 + 2*m2 + 1) * HD + cq * 4);
            Vs[m2][cq*4+0] = pack_bf16(v0.x, v1.x);
            Vs[m2][cq*4+1] = pack_bf16(v0.y, v1.y);
            Vs[m2][cq*4+2] = pack_bf16(v0.z, v1.z);
            Vs[m2][cq*4+3] = pack_bf16(v0.w, v1.w);
        }
        __syncthreads();

        uint32_t* Pb = g_P + (((size_t)bh * NN + r0) * NN + c0) / 2;

        // process the 128-col tile in two 64-col halves (register economy)
        #pragma unroll
        for (int h = 0; h < 2; h++) {
            float acc[8][4];
            #pragma unroll
            for (int j = 0; j < 8; j++) {
                acc[j][0]=0.f; acc[j][1]=0.f; acc[j][2]=0.f; acc[j][3]=0.f;
            }
            #pragma unroll
            for (int kc = 0; kc < 32; kc += 8) {
                uint32_t a0 = Qs[row_l    ][kc + qd];
                uint32_t a1 = Qs[row_l + 8][kc + qd];
                uint32_t a2 = Qs[row_l    ][kc + qd + 4];
                uint32_t a3 = Qs[row_l + 8][kc + qd + 4];
                #pragma unroll
                for (int j = 0; j < 8; j++) {
                    uint32_t b0 = Ks[h*64 + j*8 + g][kc + qd];
                    uint32_t b1 = Ks[h*64 + j*8 + g][kc + qd + 4];
                    mma_tf32(acc[j][0], acc[j][1], acc[j][2], acc[j][3],
                             a0, a1, a2, a3, b0, b1);
                }
            }

            // exp + pack + store + rowsums
            uint32_t pl[8], ph[8];
            #pragma unroll
            for (int j = 0; j < 8; j++) {
                float e0 = __expf(acc[j][0]);
                float e1 = __expf(acc[j][1]);
                float e2 = __expf(acc[j][2]);
                float e3 = __expf(acc[j][3]);
                pl[j] = pack_bf16(e0, e1);
                ph[j] = pack_bf16(e2, e3);
                int colp = (h*64 + j*8 + qd*2) >> 1;
                Pb[(size_t)(row_l    ) * (NN/2) + colp] = pl[j];
                Pb[(size_t)(row_l + 8) * (NN/2) + colp] = ph[j];
                rs_lo += e0 + e1;
                rs_hi += e2 + e3;
            }

            // fused y += P_half * v_half : 4 k-chunks of 16 rows each
            #pragma unroll
            for (int u = 0; u < 4; u++) {
                uint32_t a0 = pl[2*u], a1 = ph[2*u], a2 = pl[2*u+1], a3 = ph[2*u+1];
                int pr = (4*h + u) * 8;   // Vs pair-row base for this k-chunk
                #pragma unroll
                for (int j2 = 0; j2 < 4; j2++) {
                    uint32_t b0 = Vs[pr + qd    ][j2*8 + g];
                    uint32_t b1 = Vs[pr + qd + 4][j2*8 + g];
                    mma_bf16(accy[j2][0], accy[j2][1], accy[j2][2], accy[j2][3],
                             a0, a1, a2, a3, b0, b1);
                }
            }
        }
        __syncthreads();
    }

    // rowsum reduce over qd lanes
    rs_lo += __shfl_xor_sync(0xffffffffu, rs_lo, 1);
    rs_lo += __shfl_xor_sync(0xffffffffu, rs_lo, 2);
    rs_hi += __shfl_xor_sync(0xffffffffu, rs_hi, 1);
    rs_hi += __shfl_xor_sync(0xffffffffu, rs_hi, 2);
    if (qd == 0) {
        g_rowsum[bh * NN + r0 + row_l]     = rs_lo;
        g_rowsum[bh * NN + r0 + row_l + 8] = rs_hi;
    }
    // broadcast reduced sums back to all qd lanes (lane qd==0 of each group holds it)
    float rsum_lo = __shfl_sync(0xffffffffu, rs_lo, g*4);
    float rsum_hi = __shfl_sync(0xffffffffu, rs_hi, g*4);

    // epilogue: t1 = y / rowsum ; g_acc += c1 * t1
    const int r_lo = r0 + row_l;
    const int r_hi = r_lo + 8;
    const float inv_lo = 1.0f / rsum_lo;
    const float inv_hi = 1.0f / rsum_hi;
    #pragma unroll
    for (int j = 0; j < 4; j++) {
        int col = j*8 + qd*2;
        size_t o_lo = ((size_t)bh * NN + r_lo) * HD + col;
        size_t o_hi = ((size_t)bh * NN + r_hi) * HD + col;
        float2 lo = make_float2(accy[j][0] * inv_lo, accy[j][1] * inv_lo);
        float2 hi = make_float2(accy[j][2] * inv_hi, accy[j][3] * inv_hi);
        *(float2*)(g_t1 + o_lo) = lo;
        *(float2*)(g_t1 + o_hi) = hi;
        float2 a_lo = *(float2*)(g_acc + o_lo);
        float2 a_hi = *(float2*)(g_acc + o_hi);
        a_lo.x += c1 * lo.x; a_lo.y += c1 * lo.y;
        a_hi.x += c1 * hi.x; a_hi.y += c1 * hi.y;
        *(float2*)(g_acc + o_lo) = a_lo;
        *(float2*)(g_acc + o_hi) = a_hi;
    }
}

// ============================================================
// Kernel 3: t_out = diag(1/rowsum) * P * t_in ; g_acc += c_k * t_out
// bf16 mma, double-buffered cp.async pipeline on the P stream.
// grid (16 row-tiles of 128, 32 bh), block 256 (8 warps).
// Dynamic smem: Ps[2][128][68] + Ts[2][64][40].
// ============================================================
#define PS_STRIDE 68
#define TS_STRIDE 40
#define PS_BUF_U32 (128*PS_STRIDE)
#define TS_BUF_U32 (64*TS_STRIDE)
#define PASS_SMEM_BYTES ((2*PS_BUF_U32 + 2*TS_BUF_U32)*4)

__global__ void pass_kernel(const float* __restrict__ coeffs, int pass) {
    extern __shared__ uint32_t sm[];
    uint32_t* Ps0 = sm;
    uint32_t* Ts0 = sm + 2*PS_BUF_U32;

    const float* tin  = (pass & 1) ? g_t0 : g_t1;
    float*       tout = (pass & 1) ? g_t1 : g_t0;

    const int bh = blockIdx.y;
    const int r0 = blockIdx.x * 128;
    const float c = coeffs[(bh & 7) * 4 + pass];

    const int tid  = threadIdx.x;
    const int warp = tid >> 5;
    const int lane = tid & 31;
    const int g  = lane >> 2;
    const int qd = lane & 3;

    float acc[4][4];
    #pragma unroll
    for (int j = 0; j < 4; j++) {
        acc[j][0]=0.f; acc[j][1]=0.f; acc[j][2]=0.f; acc[j][3]=0.f;
    }

    const uint32_t* Prow = g_P + ((size_t)bh * NN + r0) * (NN/2);
    const float* Tb = tin + (size_t)bh * NN * HD;
    const int row_l = warp * 16 + g;

    // prologue: async-load P chunk 0 into buffer 0
    {
        uint32_t* Pd = Ps0;
        for (int l = tid; l < 2048; l += 256) {
            int r = l >> 4, mq = l & 15;
            uint32_t s = (uint32_t)__cvta_generic_to_shared(Pd + r*PS_STRIDE + mq*4);
            cp16(s, Prow + (size_t)r * (NN/2) + mq*4);
        }
        asm volatile("cp.async.commit_group;");
    }

    for (int i = 0; i < 16; i++) {
        const int m0 = i * 128;
        const int buf = i & 1;

        // issue async load of next P chunk into the other buffer
        if (i < 15) {
            uint32_t* Pd = Ps0 + (buf^1) * PS_BUF_U32;
            const uint32_t* Pg = Prow + (m0 + 128)/2;
            for (int l = tid; l < 2048; l += 256) {
                int r = l >> 4, mq = l & 15;
                uint32_t s = (uint32_t)__cvta_generic_to_shared(Pd + r*PS_STRIDE + mq*4);
                cp16(s, Pg + (size_t)r * (NN/2) + mq*4);
            }
            asm volatile("cp.async.commit_group;");
        }

        // stage t tile for chunk i (sync loads overlap with async P stream)
        {
            uint32_t* Td = Ts0 + buf * TS_BUF_U32;
            for (int l = tid; l < 512; l += 256) {
                int m2 = l >> 3, cq = l & 7;
                float4 v0 = *(const float4*)(Tb + (size_t)(m0 + 2*m2    ) * HD + cq * 4);
                float4 v1 = *(const float4*)(Tb + (size_t)(m0 + 2*m2 + 1) * HD + cq * 4);
                Td[m2*TS_STRIDE + cq*4+0] = pack_bf16(v0.x, v1.x);
                Td[m2*TS_STRIDE + cq*4+1] = pack_bf16(v0.y, v1.y);
                Td[m2*TS_STRIDE + cq*4+2] = pack_bf16(v0.z, v1.z);
                Td[m2*TS_STRIDE + cq*4+3] = pack_bf16(v0.w, v1.w);
            }
        }

        if (i < 15) { asm volatile("cp.async.wait_group 1;"); }
        else        { asm volatile("cp.async.wait_group 0;"); }
        __syncthreads();

        const uint32_t* Pc = Ps0 + buf * PS_BUF_U32;
        const uint32_t* Tc = Ts0 + buf * TS_BUF_U32;

        #pragma unroll
        for (int kc = 0; kc < 64; kc += 8) {       // pair units (16 bf16 per step)
            uint32_t a0 = Pc[(row_l    )*PS_STRIDE + kc + qd];
            uint32_t a1 = Pc[(row_l + 8)*PS_STRIDE + kc + qd];
            uint32_t a2 = Pc[(row_l    )*PS_STRIDE + kc + qd + 4];
            uint32_t a3 = Pc[(row_l + 8)*PS_STRIDE + kc + qd + 4];
            #pragma unroll
            for (int j = 0; j < 4; j++) {
                uint32_t b0 = Tc[(kc + qd    )*TS_STRIDE + j*8 + g];
                uint32_t b1 = Tc[(kc + qd + 4)*TS_STRIDE + j*8 + g];
                mma_bf16(acc[j][0], acc[j][1], acc[j][2], acc[j][3],
                         a0, a1, a2, a3, b0, b1);
            }
        }
        __syncthreads();
    }

    const int r_lo = r0 + row_l;
    const int r_hi = r_lo + 8;
    const float inv_lo = 1.0f / g_rowsum[bh * NN + r_lo];
    const float inv_hi = 1.0f / g_rowsum[bh * NN + r_hi];
    #pragma unroll
    for (int j = 0; j < 4; j++) {
        int col = j*8 + qd*2;
        size_t o_lo = ((size_t)bh * NN + r_lo) * HD + col;
        size_t o_hi = ((size_t)bh * NN + r_hi) * HD + col;
        float2 lo = make_float2(acc[j][0] * inv_lo, acc[j][1] * inv_lo);
        float2 hi = make_float2(acc[j][2] * inv_hi, acc[j][3] * inv_hi);
        if (pass != 3) {                  // final pass: tout never read again
            *(float2*)(tout + o_lo) = lo;
            *(float2*)(tout + o_hi) = hi;
        }
        float2 a_lo = *(float2*)(g_acc + o_lo);
        float2 a_hi = *(float2*)(g_acc + o_hi);
        a_lo.x += c * lo.x; a_lo.y += c * lo.y;
        a_hi.x += c * hi.x; a_hi.y += c * hi.y;
        *(float2*)(g_acc + o_lo) = a_lo;
        *(float2*)(g_acc + o_hi) = a_hi;
    }
}

// ============================================================
// Kernel 4: out = merged(g_acc) @ Wo + bo  (scalar fp32 — small)
// ============================================================
__global__ void outproj_kernel(const float* __restrict__ Wo,
                               const float* __restrict__ bo,
                               float* __restrict__ out) {
    const int m0 = blockIdx.x * 64;
    const int c0 = blockIdx.y * 64;

    __shared__ float Ms[64][33];
    __shared__ float Ws[32][64];

    const int tid = threadIdx.x;
    const int ty = tid >> 4, tx = tid & 15;

    float acc[4][4] = {};

    for (int k0 = 0; k0 < DD; k0 += 32) {
        int hh = k0 >> 5;
        for (int l = tid; l < 512; l += 256) {
            int r = l >> 3, kq = l & 7;
            int m = m0 + r;
            int b_ = m >> 11, n = m & 2047;
            float4 v = *(const float4*)(g_acc + ((size_t)(b_ * HH + hh) * NN + n) * HD + kq * 4);
            Ms[r][kq*4+0] = v.x; Ms[r][kq*4+1] = v.y;
            Ms[r][kq*4+2] = v.z; Ms[r][kq*4+3] = v.w;
        }
        for (int l = tid; l < 512; l += 256) {
            int k = l >> 4, cq = l & 15;
            *(float4*)&Ws[k][cq*4] = *(const float4*)(Wo + (size_t)(k0 + k) * DD + c0 + cq * 4);
        }
        __syncthreads();
        #pragma unroll
        for (int kk = 0; kk < 32; kk++) {
            float a0 = Ms[ty*4+0][kk];
            float a1 = Ms[ty*4+1][kk];
            float a2 = Ms[ty*4+2][kk];
            float a3 = Ms[ty*4+3][kk];
            float4 b = *(float4*)&Ws[kk][tx*4];
            acc[0][0] += a0*b.x; acc[0][1] += a0*b.y; acc[0][2] += a0*b.z; acc[0][3] += a0*b.w;
            acc[1][0] += a1*b.x; acc[1][1] += a1*b.y; acc[1][2] += a1*b.z; acc[1][3] += a1*b.w;
            acc[2][0] += a2*b.x; acc[2][1] += a2*b.y; acc[2][2] += a2*b.z; acc[2][3] += a2*b.w;
            acc[3][0] += a3*b.x; acc[3][1] += a3*b.y; acc[3][2] += a3*b.z; acc[3][3] += a3*b.w;
        }
        __syncthreads();
    }

    #pragma unroll
    for (int i = 0; i < 4; i++) {
        int m = m0 + ty * 4 + i;
        #pragma unroll
        for (int j = 0; j < 4; j++) {
            int cc = c0 + tx * 4 + j;
            out[(size_t)m * DD + cc] = acc[i][j] + bo[cc];
        }
    }
}

// ============================================================
extern "C" void kernel_launch(void* const* d_in, const int* in_sizes, int n_in,
                              void* d_out, int out_size) {
    const float* x      = (const float*)d_in[0];
    const float* Wq     = (const float*)d_in[1];
    const float* bq     = (const float*)d_in[2];
    const float* Wk     = (const float*)d_in[3];
    const float* bk     = (const float*)d_in[4];
    const float* Wv     = (const float*)d_in[5];
    const float* bv     = (const float*)d_in[6];
    const float* Wo     = (const float*)d_in[7];
    const float* bo     = (const float*)d_in[8];
    const float* coeffs = (const float*)d_in[9];
    float* out = (float*)d_out;

    static int smem_set = 0;
    if (!smem_set) {
        cudaFuncSetAttribute(pass_kernel,
                             cudaFuncAttributeMaxDynamicSharedMemorySize,
                             PASS_SMEM_BYTES);
        smem_set = 1;
    }

    dim3 g1(128, 4, 3);
    qkv_kernel<<<g1, 256>>>(x, Wq, bq, Wk, bk, Wv, bv, coeffs);

    dim3 g2(16, 32);
    attnP_kernel<<<g2, 256>>>(coeffs);

    pass_kernel<<<g2, 256, PASS_SMEM_BYTES>>>(coeffs, 2);
    pass_kernel<<<g2, 256, PASS_SMEM_BYTES>>>(coeffs, 3);

    dim3 g4(128, 4);
    outproj_kernel<<<g4, 256>>>(Wo, bo, out);
}

// round 9
// speedup vs baseline: 1.4980x; 1.4980x over previous
#include <cuda_runtime.h>
#include <math.h>
#include <stdint.h>

#define HH 8
#define HD 32
#define BB 4
#define NN 2048
#define DD 256
#define BH (BB*HH)   // 32

// ---- device scratch (static: allocation-free rule) ----
__device__ float g_Q[(size_t)BH*NN*HD];
__device__ float g_K[(size_t)BH*NN*HD];
__device__ uint32_t g_P[(size_t)BH*NN*NN/2];   // bf16 pairs, 256 MB
__device__ float g_rowsum[BH*NN];
__device__ float g_t0[(size_t)BH*NN*HD];
__device__ float g_t1[(size_t)BH*NN*HD];
__device__ float g_acc[(size_t)BH*NN*HD];

__device__ __forceinline__ uint32_t f2tf(float f) {
    uint32_t r;
    asm("cvt.rna.tf32.f32 %0, %1;" : "=r"(r) : "f"(f));
    return r;
}

// pack two fp32 -> bf16x2 (lo in low half, hi in high half)
__device__ __forceinline__ uint32_t pack_bf16(float lo, float hi) {
    uint32_t r;
    asm("cvt.rn.bf16x2.f32 %0, %1, %2;" : "=r"(r) : "f"(hi), "f"(lo));
    return r;
}

__device__ __forceinline__ void mma_tf32(float& d0, float& d1, float& d2, float& d3,
                                         uint32_t a0, uint32_t a1, uint32_t a2, uint32_t a3,
                                         uint32_t b0, uint32_t b1) {
    asm("mma.sync.aligned.m16n8k8.row.col.f32.tf32.tf32.f32 "
        "{%0,%1,%2,%3},{%4,%5,%6,%7},{%8,%9},{%0,%1,%2,%3};"
        : "+f"(d0), "+f"(d1), "+f"(d2), "+f"(d3)
        : "r"(a0), "r"(a1), "r"(a2), "r"(a3), "r"(b0), "r"(b1));
}

__device__ __forceinline__ void mma_bf16(float& d0, float& d1, float& d2, float& d3,
                                         uint32_t a0, uint32_t a1, uint32_t a2, uint32_t a3,
                                         uint32_t b0, uint32_t b1) {
    asm("mma.sync.aligned.m16n8k16.row.col.f32.bf16.bf16.f32 "
        "{%0,%1,%2,%3},{%4,%5,%6,%7},{%8,%9},{%0,%1,%2,%3};"
        : "+f"(d0), "+f"(d1), "+f"(d2), "+f"(d3)
        : "r"(a0), "r"(a1), "r"(a2), "r"(a3), "r"(b0), "r"(b1));
}

__device__ __forceinline__ void cp16(uint32_t saddr, const void* gptr) {
    asm volatile("cp.async.cg.shared.global [%0], [%1], 16;" :: "r"(saddr), "l"(gptr));
}

// ============================================================
// Kernel 1: QKV projection + head split. (scalar fp32 — small)
// ============================================================
__global__ void qkv_kernel(const float* __restrict__ x,
                           const float* __restrict__ Wq, const float* __restrict__ bq,
                           const float* __restrict__ Wk, const float* __restrict__ bk,
                           const float* __restrict__ Wv, const float* __restrict__ bv,
                           const float* __restrict__ coeffs) {
    const int mat = blockIdx.z;
    const float* W    = (mat == 0) ? Wq : ((mat == 1) ? Wk : Wv);
    const float* bias = (mat == 0) ? bq : ((mat == 1) ? bk : bv);
    const int m0 = blockIdx.x * 64;
    const int c0 = blockIdx.y * 64;

    __shared__ float Xs[64][33];
    __shared__ float Ws[32][64];

    const int tid = threadIdx.x;
    const int ty = tid >> 4, tx = tid & 15;

    float acc[4][4] = {};

    for (int k0 = 0; k0 < DD; k0 += 32) {
        for (int l = tid; l < 512; l += 256) {
            int r = l >> 3, kq = l & 7;
            float4 v = *(const float4*)(x + (size_t)(m0 + r) * DD + k0 + kq * 4);
            Xs[r][kq*4+0] = v.x; Xs[r][kq*4+1] = v.y;
            Xs[r][kq*4+2] = v.z; Xs[r][kq*4+3] = v.w;
        }
        for (int l = tid; l < 512; l += 256) {
            int k = l >> 4, cq = l & 15;
            *(float4*)&Ws[k][cq*4] = *(const float4*)(W + (size_t)(k0 + k) * DD + c0 + cq * 4);
        }
        __syncthreads();
        #pragma unroll
        for (int kk = 0; kk < 32; kk++) {
            float a0 = Xs[ty*4+0][kk];
            float a1 = Xs[ty*4+1][kk];
            float a2 = Xs[ty*4+2][kk];
            float a3 = Xs[ty*4+3][kk];
            float4 b = *(float4*)&Ws[kk][tx*4];
            acc[0][0] += a0*b.x; acc[0][1] += a0*b.y; acc[0][2] += a0*b.z; acc[0][3] += a0*b.w;
            acc[1][0] += a1*b.x; acc[1][1] += a1*b.y; acc[1][2] += a1*b.z; acc[1][3] += a1*b.w;
            acc[2][0] += a2*b.x; acc[2][1] += a2*b.y; acc[2][2] += a2*b.z; acc[2][3] += a2*b.w;
            acc[3][0] += a3*b.x; acc[3][1] += a3*b.y; acc[3][2] += a3*b.z; acc[3][3] += a3*b.w;
        }
        __syncthreads();
    }

    #pragma unroll
    for (int i = 0; i < 4; i++) {
        int m = m0 + ty * 4 + i;
        int b_ = m >> 11, n = m & 2047;
        #pragma unroll
        for (int j = 0; j < 4; j++) {
            int c = c0 + tx * 4 + j;
            float val = acc[i][j] + bias[c];
            int h = c >> 5, d = c & 31;
            size_t idx = ((size_t)(b_ * HH + h) * NN + n) * HD + d;
            if (mat == 0)      g_Q[idx] = val;
            else if (mat == 1) g_K[idx] = val;
            else {
                g_t0[idx]  = val;
                g_acc[idx] = coeffs[h * 4] * val;   // c0 * v
            }
        }
    }
}

// ============================================================
// Kernel 2: P = exp(Q K^T * scale) via tf32 mma, store bf16 pairs + rowsums.
// grid (16 row-tiles of 128, 32 bh), block 256 (8 warps).  [R5 version]
// ============================================================
__global__ void attnP_kernel() {
    const int bh = blockIdx.y;
    const int r0 = blockIdx.x * 128;

    __shared__ uint32_t Qs[128][36];   // tf32 bits
    __shared__ uint32_t Ks[128][36];

    const int tid  = threadIdx.x;
    const int warp = tid >> 5;
    const int lane = tid & 31;
    const int g  = lane >> 2;   // 0..7
    const int qd = lane & 3;    // 0..3

    const float scale = 0.17677669529663687f;  // 1/sqrt(32), folded into Q

    const float* Qb = g_Q + ((size_t)bh * NN + r0) * HD;
    for (int l = tid; l < 1024; l += 256) {
        int r = l >> 3, kq = l & 7;
        float4 v = *(const float4*)(Qb + (size_t)r * HD + kq * 4);
        uint4 u;
        u.x = f2tf(v.x * scale); u.y = f2tf(v.y * scale);
        u.z = f2tf(v.z * scale); u.w = f2tf(v.w * scale);
        *(uint4*)&Qs[r][kq*4] = u;
    }
    __syncthreads();

    const int row_l = warp * 16 + g;
    float rs_lo = 0.f, rs_hi = 0.f;

    for (int ct = 0; ct < 16; ct++) {
        const int c0 = ct * 128;
        const float* Kb = g_K + ((size_t)bh * NN + c0) * HD;
        for (int l = tid; l < 1024; l += 256) {
            int r = l >> 3, kq = l & 7;
            float4 v = *(const float4*)(Kb + (size_t)r * HD + kq * 4);
            uint4 u;
            u.x = f2tf(v.x); u.y = f2tf(v.y);
            u.z = f2tf(v.z); u.w = f2tf(v.w);
            *(uint4*)&Ks[r][kq*4] = u;
        }
        __syncthreads();

        float acc[16][4];
        #pragma unroll
        for (int j = 0; j < 16; j++) {
            acc[j][0] = 0.f; acc[j][1] = 0.f; acc[j][2] = 0.f; acc[j][3] = 0.f;
        }

        #pragma unroll
        for (int kc = 0; kc < 32; kc += 8) {
            uint32_t a0 = Qs[row_l    ][kc + qd];
            uint32_t a1 = Qs[row_l + 8][kc + qd];
            uint32_t a2 = Qs[row_l    ][kc + qd + 4];
            uint32_t a3 = Qs[row_l + 8][kc + qd + 4];
            #pragma unroll
            for (int j = 0; j < 16; j++) {
                uint32_t b0 = Ks[j*8 + g][kc + qd];
                uint32_t b1 = Ks[j*8 + g][kc + qd + 4];
                mma_tf32(acc[j][0], acc[j][1], acc[j][2], acc[j][3],
                         a0, a1, a2, a3, b0, b1);
            }
        }

        // epilogue: exp, pack bf16 pairs, store, rowsum partials
        uint32_t* Pb = g_P + (((size_t)bh * NN + r0) * NN + c0) / 2;
        #pragma unroll
        for (int j = 0; j < 16; j++) {
            int colp = (j*8 + qd*2) >> 1;            // pair index within 128-col chunk
            float e0 = __expf(acc[j][0]);
            float e1 = __expf(acc[j][1]);
            float e2 = __expf(acc[j][2]);
            float e3 = __expf(acc[j][3]);
            Pb[(size_t)(row_l    ) * (NN/2) + colp] = pack_bf16(e0, e1);
            Pb[(size_t)(row_l + 8) * (NN/2) + colp] = pack_bf16(e2, e3);
            rs_lo += e0 + e1;
            rs_hi += e2 + e3;
        }
        __syncthreads();
    }

    rs_lo += __shfl_xor_sync(0xffffffffu, rs_lo, 1);
    rs_lo += __shfl_xor_sync(0xffffffffu, rs_lo, 2);
    rs_hi += __shfl_xor_sync(0xffffffffu, rs_hi, 1);
    rs_hi += __shfl_xor_sync(0xffffffffu, rs_hi, 2);
    if (qd == 0) {
        g_rowsum[bh * NN + r0 + row_l]     = rs_lo;
        g_rowsum[bh * NN + r0 + row_l + 8] = rs_hi;
    }
}

// ============================================================
// Kernel 3: t_out = diag(1/rowsum) * P * t_in ; g_acc += c_k * t_out
// bf16 mma, cp.async double-buffered over 64-wide m-chunks.
// Static smem 47 KB -> same occupancy as single-buffer R5.
// grid (16 row-tiles of 128, 32 bh), block 256 (8 warps).
// ============================================================
__global__ void pass_kernel(const float* __restrict__ coeffs, int pass) {
    __shared__ uint32_t Ps[2][128][36];   // bf16 pairs; 64 m per chunk (32 u32/row)
    __shared__ uint32_t Ts[2][32][40];    // bf16 row-pairs of t chunk

    const float* tin  = (pass & 1) ? g_t0 : g_t1;
    float*       tout = (pass & 1) ? g_t1 : g_t0;

    const int bh = blockIdx.y;
    const int r0 = blockIdx.x * 128;
    const float c = coeffs[(bh & 7) * 4 + pass];

    const int tid  = threadIdx.x;
    const int warp = tid >> 5;
    const int lane = tid & 31;
    const int g  = lane >> 2;
    const int qd = lane & 3;

    float acc[4][4];
    #pragma unroll
    for (int j = 0; j < 4; j++) {
        acc[j][0]=0.f; acc[j][1]=0.f; acc[j][2]=0.f; acc[j][3]=0.f;
    }

    const uint32_t* Prow = g_P + ((size_t)bh * NN + r0) * (NN/2);
    const float* Tb = tin + (size_t)bh * NN * HD;
    const int row_l = warp * 16 + g;

    // prologue: async-load P chunk 0 (128 rows x 32 u32) into buffer 0
    for (int l = tid; l < 1024; l += 256) {
        int r = l >> 3, mq = l & 7;
        uint32_t s = (uint32_t)__cvta_generic_to_shared(&Ps[0][r][mq*4]);
        cp16(s, Prow + (size_t)r * (NN/2) + mq*4);
    }
    asm volatile("cp.async.commit_group;");

    for (int i = 0; i < 32; i++) {
        const int m0 = i * 64;
        const int buf = i & 1;

        // issue async load of next P chunk into the other buffer
        if (i < 31) {
            const uint32_t* Pg = Prow + (m0 + 64)/2;
            for (int l = tid; l < 1024; l += 256) {
                int r = l >> 3, mq = l & 7;
                uint32_t s = (uint32_t)__cvta_generic_to_shared(&Ps[buf^1][r][mq*4]);
                cp16(s, Pg + (size_t)r * (NN/2) + mq*4);
            }
            asm volatile("cp.async.commit_group;");
        }

        // stage t chunk i (64 rows -> 32 bf16 pair-rows), one item per thread
        {
            int m2 = tid >> 3, cq = tid & 7;
            float4 v0 = *(const float4*)(Tb + (size_t)(m0 + 2*m2    ) * HD + cq * 4);
            float4 v1 = *(const float4*)(Tb + (size_t)(m0 + 2*m2 + 1) * HD + cq * 4);
            Ts[buf][m2][cq*4+0] = pack_bf16(v0.x, v1.x);
            Ts[buf][m2][cq*4+1] = pack_bf16(v0.y, v1.y);
            Ts[buf][m2][cq*4+2] = pack_bf16(v0.z, v1.z);
            Ts[buf][m2][cq*4+3] = pack_bf16(v0.w, v1.w);
        }

        if (i < 31) { asm volatile("cp.async.wait_group 1;"); }
        else        { asm volatile("cp.async.wait_group 0;"); }
        __syncthreads();

        #pragma unroll
        for (int kc = 0; kc < 32; kc += 8) {       // pair units (16 bf16 per step)
            uint32_t a0 = Ps[buf][row_l    ][kc + qd];
            uint32_t a1 = Ps[buf][row_l + 8][kc + qd];
            uint32_t a2 = Ps[buf][row_l    ][kc + qd + 4];
            uint32_t a3 = Ps[buf][row_l + 8][kc + qd + 4];
            #pragma unroll
            for (int j = 0; j < 4; j++) {
                uint32_t b0 = Ts[buf][kc + qd    ][j*8 + g];
                uint32_t b1 = Ts[buf][kc + qd + 4][j*8 + g];
                mma_bf16(acc[j][0], acc[j][1], acc[j][2], acc[j][3],
                         a0, a1, a2, a3, b0, b1);
            }
        }
        __syncthreads();
    }

    const int r_lo = r0 + row_l;
    const int r_hi = r_lo + 8;
    const float inv_lo = 1.0f / g_rowsum[bh * NN + r_lo];
    const float inv_hi = 1.0f / g_rowsum[bh * NN + r_hi];
    #pragma unroll
    for (int j = 0; j < 4; j++) {
        int col = j*8 + qd*2;
        size_t o_lo = ((size_t)bh * NN + r_lo) * HD + col;
        size_t o_hi = ((size_t)bh * NN + r_hi) * HD + col;
        float2 lo = make_float2(acc[j][0] * inv_lo, acc[j][1] * inv_lo);
        float2 hi = make_float2(acc[j][2] * inv_hi, acc[j][3] * inv_hi);
        if (pass != 3) {                  // final pass: tout never read again
            *(float2*)(tout + o_lo) = lo;
            *(float2*)(tout + o_hi) = hi;
        }
        float2 a_lo = *(float2*)(g_acc + o_lo);
        float2 a_hi = *(float2*)(g_acc + o_hi);
        a_lo.x += c * lo.x; a_lo.y += c * lo.y;
        a_hi.x += c * hi.x; a_hi.y += c * hi.y;
        *(float2*)(g_acc + o_lo) = a_lo;
        *(float2*)(g_acc + o_hi) = a_hi;
    }
}

// ============================================================
// Kernel 4: out = merged(g_acc) @ Wo + bo  (scalar fp32 — small)
// ============================================================
__global__ void outproj_kernel(const float* __restrict__ Wo,
                               const float* __restrict__ bo,
                               float* __restrict__ out) {
    const int m0 = blockIdx.x * 64;
    const int c0 = blockIdx.y * 64;

    __shared__ float Ms[64][33];
    __shared__ float Ws[32][64];

    const int tid = threadIdx.x;
    const int ty = tid >> 4, tx = tid & 15;

    float acc[4][4] = {};

    for (int k0 = 0; k0 < DD; k0 += 32) {
        int hh = k0 >> 5;
        for (int l = tid; l < 512; l += 256) {
            int r = l >> 3, kq = l & 7;
            int m = m0 + r;
            int b_ = m >> 11, n = m & 2047;
            float4 v = *(const float4*)(g_acc + ((size_t)(b_ * HH + hh) * NN + n) * HD + kq * 4);
            Ms[r][kq*4+0] = v.x; Ms[r][kq*4+1] = v.y;
            Ms[r][kq*4+2] = v.z; Ms[r][kq*4+3] = v.w;
        }
        for (int l = tid; l < 512; l += 256) {
            int k = l >> 4, cq = l & 15;
            *(float4*)&Ws[k][cq*4] = *(const float4*)(Wo + (size_t)(k0 + k) * DD + c0 + cq * 4);
        }
        __syncthreads();
        #pragma unroll
        for (int kk = 0; kk < 32; kk++) {
            float a0 = Ms[ty*4+0][kk];
            float a1 = Ms[ty*4+1][kk];
            float a2 = Ms[ty*4+2][kk];
            float a3 = Ms[ty*4+3][kk];
            float4 b = *(float4*)&Ws[kk][tx*4];
            acc[0][0] += a0*b.x; acc[0][1] += a0*b.y; acc[0][2] += a0*b.z; acc[0][3] += a0*b.w;
            acc[1][0] += a1*b.x; acc[1][1] += a1*b.y; acc[1][2] += a1*b.z; acc[1][3] += a1*b.w;
            acc[2][0] += a2*b.x; acc[2][1] += a2*b.y; acc[2][2] += a2*b.z; acc[2][3] += a2*b.w;
            acc[3][0] += a3*b.x; acc[3][1] += a3*b.y; acc[3][2] += a3*b.z; acc[3][3] += a3*b.w;
        }
        __syncthreads();
    }

    #pragma unroll
    for (int i = 0; i < 4; i++) {
        int m = m0 + ty * 4 + i;
        #pragma unroll
        for (int j = 0; j < 4; j++) {
            int cc = c0 + tx * 4 + j;
            out[(size_t)m * DD + cc] = acc[i][j] + bo[cc];
        }
    }
}

// ============================================================
extern "C" void kernel_launch(void* const* d_in, const int* in_sizes, int n_in,
                              void* d_out, int out_size) {
    const float* x      = (const float*)d_in[0];
    const float* Wq     = (const float*)d_in[1];
    const float* bq     = (const float*)d_in[2];
    const float* Wk     = (const float*)d_in[3];
    const float* bk     = (const float*)d_in[4];
    const float* Wv     = (const float*)d_in[5];
    const float* bv     = (const float*)d_in[6];
    const float* Wo     = (const float*)d_in[7];
    const float* bo     = (const float*)d_in[8];
    const float* coeffs = (const float*)d_in[9];
    float* out = (float*)d_out;

    dim3 g1(128, 4, 3);
    qkv_kernel<<<g1, 256>>>(x, Wq, bq, Wk, bk, Wv, bv, coeffs);

    dim3 g2(16, 32);
    attnP_kernel<<<g2, 256>>>();

    pass_kernel<<<g2, 256>>>(coeffs, 1);
    pass_kernel<<<g2, 256>>>(coeffs, 2);
    pass_kernel<<<g2, 256>>>(coeffs, 3);

    dim3 g4(128, 4);
    outproj_kernel<<<g4, 256>>>(Wo, bo, out);
}

// round 12
// speedup vs baseline: 1.6399x; 1.0947x over previous
#include <cuda_runtime.h>
#include <math.h>
#include <stdint.h>

#define HH 8
#define HD 32
#define BB 4
#define NN 2048
#define DD 256
#define BH (BB*HH)   // 32

// ---- device scratch (static: allocation-free rule) ----
__device__ float g_Q[(size_t)BH*NN*HD];
__device__ float g_K[(size_t)BH*NN*HD];
__device__ uint32_t g_P[(size_t)BH*NN*NN/2];   // bf16 pairs, 256 MB
__device__ float g_rowsum[BH*NN];
__device__ float g_t0[(size_t)BH*NN*HD];
__device__ float g_t1[(size_t)BH*NN*HD];
__device__ float g_acc[(size_t)BH*NN*HD];

__device__ __forceinline__ uint32_t f2tf(float f) {
    uint32_t r;
    asm("cvt.rna.tf32.f32 %0, %1;" : "=r"(r) : "f"(f));
    return r;
}

// pack two fp32 -> bf16x2 (lo in low half, hi in high half)
__device__ __forceinline__ uint32_t pack_bf16(float lo, float hi) {
    uint32_t r;
    asm("cvt.rn.bf16x2.f32 %0, %1, %2;" : "=r"(r) : "f"(hi), "f"(lo));
    return r;
}

__device__ __forceinline__ void mma_tf32(float& d0, float& d1, float& d2, float& d3,
                                         uint32_t a0, uint32_t a1, uint32_t a2, uint32_t a3,
                                         uint32_t b0, uint32_t b1) {
    asm("mma.sync.aligned.m16n8k8.row.col.f32.tf32.tf32.f32 "
        "{%0,%1,%2,%3},{%4,%5,%6,%7},{%8,%9},{%0,%1,%2,%3};"
        : "+f"(d0), "+f"(d1), "+f"(d2), "+f"(d3)
        : "r"(a0), "r"(a1), "r"(a2), "r"(a3), "r"(b0), "r"(b1));
}

__device__ __forceinline__ void mma_bf16(float& d0, float& d1, float& d2, float& d3,
                                         uint32_t a0, uint32_t a1, uint32_t a2, uint32_t a3,
                                         uint32_t b0, uint32_t b1) {
    asm("mma.sync.aligned.m16n8k16.row.col.f32.bf16.bf16.f32 "
        "{%0,%1,%2,%3},{%4,%5,%6,%7},{%8,%9},{%0,%1,%2,%3};"
        : "+f"(d0), "+f"(d1), "+f"(d2), "+f"(d3)
        : "r"(a0), "r"(a1), "r"(a2), "r"(a3), "r"(b0), "r"(b1));
}

__device__ __forceinline__ void cp16(uint32_t saddr, const void* gptr) {
    asm volatile("cp.async.cg.shared.global [%0], [%1], 16;" :: "r"(saddr), "l"(gptr));
}

// ============================================================
// Kernel 1: QKV projection + head split, 3xTF32 tensor path.
// grid (64, 4, 3): 128-row x 64-col tiles, z = which matrix.
// acc = hiA*hiB + hiA*loB + loA*hiB  (~fp32 accuracy)
// ============================================================
__global__ void qkv_kernel(const float* __restrict__ x,
                           const float* __restrict__ Wq, const float* __restrict__ bq,
                           const float* __restrict__ Wk, const float* __restrict__ bk,
                           const float* __restrict__ Wv, const float* __restrict__ bv,
                           const float* __restrict__ coeffs) {
    const int mat = blockIdx.z;
    const float* W    = (mat == 0) ? Wq : ((mat == 1) ? Wk : Wv);
    const float* bias = (mat == 0) ? bq : ((mat == 1) ? bk : bv);
    const int m0 = blockIdx.x * 128;
    const int c0 = blockIdx.y * 64;

    __shared__ uint32_t XsH[128][36];
    __shared__ uint32_t XsL[128][36];
    __shared__ uint32_t WtH[64][36];
    __shared__ uint32_t WtL[64][36];

    const int tid  = threadIdx.x;
    const int warp = tid >> 5;
    const int lane = tid & 31;
    const int g  = lane >> 2;
    const int qd = lane & 3;
    const int row_l = warp * 16 + g;

    float acc[8][4];
    #pragma unroll
    for (int j = 0; j < 8; j++) {
        acc[j][0]=0.f; acc[j][1]=0.f; acc[j][2]=0.f; acc[j][3]=0.f;
    }

    for (int k0 = 0; k0 < DD; k0 += 32) {
        // stage x tile 128x32 (hi/lo tf32)
        for (int l = tid; l < 1024; l += 256) {
            int r = l >> 3, kq = l & 7;
            float4 v = *(const float4*)(x + (size_t)(m0 + r) * DD + k0 + kq * 4);
            uint32_t hx = f2tf(v.x), hy = f2tf(v.y), hz = f2tf(v.z), hw = f2tf(v.w);
            XsH[r][kq*4+0] = hx; XsH[r][kq*4+1] = hy;
            XsH[r][kq*4+2] = hz; XsH[r][kq*4+3] = hw;
            XsL[r][kq*4+0] = f2tf(v.x - __uint_as_float(hx));
            XsL[r][kq*4+1] = f2tf(v.y - __uint_as_float(hy));
            XsL[r][kq*4+2] = f2tf(v.z - __uint_as_float(hz));
            XsL[r][kq*4+3] = f2tf(v.w - __uint_as_float(hw));
        }
        // stage W tile transposed: Wt[c][k] = W[k0+k][c0+c]
        for (int l = tid; l < 2048; l += 256) {
            int c = l & 63, k = l >> 6;
            float w = W[(size_t)(k0 + k) * DD + c0 + c];
            uint32_t h = f2tf(w);
            WtH[c][k] = h;
            WtL[c][k] = f2tf(w - __uint_as_float(h));
        }
        __syncthreads();

        #pragma unroll
        for (int kc = 0; kc < 32; kc += 8) {
            uint32_t aH0 = XsH[row_l    ][kc + qd];
            uint32_t aH1 = XsH[row_l + 8][kc + qd];
            uint32_t aH2 = XsH[row_l    ][kc + qd + 4];
            uint32_t aH3 = XsH[row_l + 8][kc + qd + 4];
            uint32_t aL0 = XsL[row_l    ][kc + qd];
            uint32_t aL1 = XsL[row_l + 8][kc + qd];
            uint32_t aL2 = XsL[row_l    ][kc + qd + 4];
            uint32_t aL3 = XsL[row_l + 8][kc + qd + 4];
            #pragma unroll
            for (int j = 0; j < 8; j++) {
                uint32_t bH0 = WtH[j*8 + g][kc + qd];
                uint32_t bH1 = WtH[j*8 + g][kc + qd + 4];
                uint32_t bL0 = WtL[j*8 + g][kc + qd];
                uint32_t bL1 = WtL[j*8 + g][kc + qd + 4];
                mma_tf32(acc[j][0], acc[j][1], acc[j][2], acc[j][3],
                         aH0, aH1, aH2, aH3, bH0, bH1);
                mma_tf32(acc[j][0], acc[j][1], acc[j][2], acc[j][3],
                         aH0, aH1, aH2, aH3, bL0, bL1);
                mma_tf32(acc[j][0], acc[j][1], acc[j][2], acc[j][3],
                         aL0, aL1, aL2, aL3, bH0, bH1);
            }
        }
        __syncthreads();
    }

    // epilogue: bias + head-split store
    #pragma unroll
    for (int j = 0; j < 8; j++) {
        #pragma unroll
        for (int half = 0; half < 2; half++) {
            int m = m0 + row_l + half * 8;
            int b_ = m >> 11, n = m & 2047;
            #pragma unroll
            for (int p = 0; p < 2; p++) {
                int c = c0 + j*8 + qd*2 + p;
                float val = acc[j][half*2 + p] + bias[c];
                int h = c >> 5, d = c & 31;
                size_t idx = ((size_t)(b_ * HH + h) * NN + n) * HD + d;
                if (mat == 0)      g_Q[idx] = val;
                else if (mat == 1) g_K[idx] = val;
                else {
                    g_t0[idx]  = val;
                    g_acc[idx] = coeffs[h * 4] * val;   // c0 * v
                }
            }
        }
    }
}

// ============================================================
// Kernel 2: P = exp(Q K^T * scale) -> bf16 + rowsums.
// cp.async double-buffered K staging; K fed as raw fp32 (tf32-truncated).
// grid (16 row-tiles of 128, 32 bh), block 256 (8 warps).
// ============================================================
__global__ void attnP_kernel() {
    const int bh = blockIdx.y;
    const int r0 = blockIdx.x * 128;

    __shared__ uint32_t Qs[128][36];      // tf32 (rna), scale folded
    __shared__ uint32_t Ks[2][128][36];   // raw fp32 bits via cp.async

    const int tid  = threadIdx.x;
    const int warp = tid >> 5;
    const int lane = tid & 31;
    const int g  = lane >> 2;   // 0..7
    const int qd = lane & 3;    // 0..3

    const float scale = 0.17677669529663687f;  // 1/sqrt(32), folded into Q

    const float* Qb = g_Q + ((size_t)bh * NN + r0) * HD;
    const float* Kb = g_K + (size_t)bh * NN * HD;

    // prologue: async-load K tile 0 (raw)
    for (int l = tid; l < 1024; l += 256) {
        int r = l >> 3, kq = l & 7;
        uint32_t s = (uint32_t)__cvta_generic_to_shared(&Ks[0][r][kq*4]);
        cp16(s, Kb + (size_t)r * HD + kq * 4);
    }
    asm volatile("cp.async.commit_group;");

    // stage Q (scaled, tf32 rna)
    for (int l = tid; l < 1024; l += 256) {
        int r = l >> 3, kq = l & 7;
        float4 v = *(const float4*)(Qb + (size_t)r * HD + kq * 4);
        uint4 u;
        u.x = f2tf(v.x * scale); u.y = f2tf(v.y * scale);
        u.z = f2tf(v.z * scale); u.w = f2tf(v.w * scale);
        *(uint4*)&Qs[r][kq*4] = u;
    }

    const int row_l = warp * 16 + g;
    float rs_lo = 0.f, rs_hi = 0.f;

    for (int ct = 0; ct < 16; ct++) {
        const int c0 = ct * 128;
        const int buf = ct & 1;

        if (ct < 15) {
            const float* Kn = Kb + (size_t)(c0 + 128) * HD;
            for (int l = tid; l < 1024; l += 256) {
                int r = l >> 3, kq = l & 7;
                uint32_t s = (uint32_t)__cvta_generic_to_shared(&Ks[buf^1][r][kq*4]);
                cp16(s, Kn + (size_t)r * HD + kq * 4);
            }
            asm volatile("cp.async.commit_group;");
        }

        if (ct < 15) { asm volatile("cp.async.wait_group 1;"); }
        else         { asm volatile("cp.async.wait_group 0;"); }
        __syncthreads();

        float acc[16][4];
        #pragma unroll
        for (int j = 0; j < 16; j++) {
            acc[j][0] = 0.f; acc[j][1] = 0.f; acc[j][2] = 0.f; acc[j][3] = 0.f;
        }

        #pragma unroll
        for (int kc = 0; kc < 32; kc += 8) {
            uint32_t a0 = Qs[row_l    ][kc + qd];
            uint32_t a1 = Qs[row_l + 8][kc + qd];
            uint32_t a2 = Qs[row_l    ][kc + qd + 4];
            uint32_t a3 = Qs[row_l + 8][kc + qd + 4];
            #pragma unroll
            for (int j = 0; j < 16; j++) {
                uint32_t b0 = Ks[buf][j*8 + g][kc + qd];
                uint32_t b1 = Ks[buf][j*8 + g][kc + qd + 4];
                mma_tf32(acc[j][0], acc[j][1], acc[j][2], acc[j][3],
                         a0, a1, a2, a3, b0, b1);
            }
        }

        // epilogue: exp, pack bf16 pairs, streaming store, rowsum partials
        uint32_t* Pb = g_P + (((size_t)bh * NN + r0) * NN + c0) / 2;
        #pragma unroll
        for (int j = 0; j < 16; j++) {
            int colp = j*4 + qd;                     // pair index within chunk
            float e0 = __expf(acc[j][0]);
            float e1 = __expf(acc[j][1]);
            float e2 = __expf(acc[j][2]);
            float e3 = __expf(acc[j][3]);
            __stcs(Pb + (size_t)(row_l    ) * (NN/2) + colp, pack_bf16(e0, e1));
            __stcs(Pb + (size_t)(row_l + 8) * (NN/2) + colp, pack_bf16(e2, e3));
            rs_lo += e0 + e1;
            rs_hi += e2 + e3;
        }
        __syncthreads();
    }

    rs_lo += __shfl_xor_sync(0xffffffffu, rs_lo, 1);
    rs_lo += __shfl_xor_sync(0xffffffffu, rs_lo, 2);
    rs_hi += __shfl_xor_sync(0xffffffffu, rs_hi, 1);
    rs_hi += __shfl_xor_sync(0xffffffffu, rs_hi, 2);
    if (qd == 0) {
        g_rowsum[bh * NN + r0 + row_l]     = rs_lo;
        g_rowsum[bh * NN + r0 + row_l + 8] = rs_hi;
    }
}

// ============================================================
// Kernel 3: t_out = diag(1/rowsum) * P * t_in ; g_acc += c_k * t_out
// bf16 mma, cp.async double-buffered over 64-wide m-chunks. [R9 best]
// ============================================================
__global__ void pass_kernel(const float* __restrict__ coeffs, int pass) {
    __shared__ uint32_t Ps[2][128][36];   // bf16 pairs; 64 m per chunk
    __shared__ uint32_t Ts[2][32][40];    // bf16 row-pairs of t chunk

    const float* tin  = (pass & 1) ? g_t0 : g_t1;
    float*       tout = (pass & 1) ? g_t1 : g_t0;

    const int bh = blockIdx.y;
    const int r0 = blockIdx.x * 128;
    const float c = coeffs[(bh & 7) * 4 + pass];

    const int tid  = threadIdx.x;
    const int warp = tid >> 5;
    const int lane = tid & 31;
    const int g  = lane >> 2;
    const int qd = lane & 3;

    float acc[4][4];
    #pragma unroll
    for (int j = 0; j < 4; j++) {
        acc[j][0]=0.f; acc[j][1]=0.f; acc[j][2]=0.f; acc[j][3]=0.f;
    }

    const uint32_t* Prow = g_P + ((size_t)bh * NN + r0) * (NN/2);
    const float* Tb = tin + (size_t)bh * NN * HD;
    const int row_l = warp * 16 + g;

    for (int l = tid; l < 1024; l += 256) {
        int r = l >> 3, mq = l & 7;
        uint32_t s = (uint32_t)__cvta_generic_to_shared(&Ps[0][r][mq*4]);
        cp16(s, Prow + (size_t)r * (NN/2) + mq*4);
    }
    asm volatile("cp.async.commit_group;");

    for (int i = 0; i < 32; i++) {
        const int m0 = i * 64;
        const int buf = i & 1;

        if (i < 31) {
            const uint32_t* Pg = Prow + (m0 + 64)/2;
            for (int l = tid; l < 1024; l += 256) {
                int r = l >> 3, mq = l & 7;
                uint32_t s = (uint32_t)__cvta_generic_to_shared(&Ps[buf^1][r][mq*4]);
                cp16(s, Pg + (size_t)r * (NN/2) + mq*4);
            }
            asm volatile("cp.async.commit_group;");
        }

        {
            int m2 = tid >> 3, cq = tid & 7;
            float4 v0 = *(const float4*)(Tb + (size_t)(m0 + 2*m2    ) * HD + cq * 4);
            float4 v1 = *(const float4*)(Tb + (size_t)(m0 + 2*m2 + 1) * HD + cq * 4);
            Ts[buf][m2][cq*4+0] = pack_bf16(v0.x, v1.x);
            Ts[buf][m2][cq*4+1] = pack_bf16(v0.y, v1.y);
            Ts[buf][m2][cq*4+2] = pack_bf16(v0.z, v1.z);
            Ts[buf][m2][cq*4+3] = pack_bf16(v0.w, v1.w);
        }

        if (i < 31) { asm volatile("cp.async.wait_group 1;"); }
        else        { asm volatile("cp.async.wait_group 0;"); }
        __syncthreads();

        #pragma unroll
        for (int kc = 0; kc < 32; kc += 8) {
            uint32_t a0 = Ps[buf][row_l    ][kc + qd];
            uint32_t a1 = Ps[buf][row_l + 8][kc + qd];
            uint32_t a2 = Ps[buf][row_l    ][kc + qd + 4];
            uint32_t a3 = Ps[buf][row_l + 8][kc + qd + 4];
            #pragma unroll
            for (int j = 0; j < 4; j++) {
                uint32_t b0 = Ts[buf][kc + qd    ][j*8 + g];
                uint32_t b1 = Ts[buf][kc + qd + 4][j*8 + g];
                mma_bf16(acc[j][0], acc[j][1], acc[j][2], acc[j][3],
                         a0, a1, a2, a3, b0, b1);
            }
        }
        __syncthreads();
    }

    const int r_lo = r0 + row_l;
    const int r_hi = r_lo + 8;
    const float inv_lo = 1.0f / g_rowsum[bh * NN + r_lo];
    const float inv_hi = 1.0f / g_rowsum[bh * NN + r_hi];
    #pragma unroll
    for (int j = 0; j < 4; j++) {
        int col = j*8 + qd*2;
        size_t o_lo = ((size_t)bh * NN + r_lo) * HD + col;
        size_t o_hi = ((size_t)bh * NN + r_hi) * HD + col;
        float2 lo = make_float2(acc[j][0] * inv_lo, acc[j][1] * inv_lo);
        float2 hi = make_float2(acc[j][2] * inv_hi, acc[j][3] * inv_hi);
        if (pass != 3) {
            *(float2*)(tout + o_lo) = lo;
            *(float2*)(tout + o_hi) = hi;
        }
        float2 a_lo = *(float2*)(g_acc + o_lo);
        float2 a_hi = *(float2*)(g_acc + o_hi);
        a_lo.x += c * lo.x; a_lo.y += c * lo.y;
        a_hi.x += c * hi.x; a_hi.y += c * hi.y;
        *(float2*)(g_acc + o_lo) = a_lo;
        *(float2*)(g_acc + o_hi) = a_hi;
    }
}

// ============================================================
// Kernel 4: out = merged(g_acc) @ Wo + bo  (scalar fp32 — small)
// ============================================================
__global__ void outproj_kernel(const float* __restrict__ Wo,
                               const float* __restrict__ bo,
                               float* __restrict__ out) {
    const int m0 = blockIdx.x * 64;
    const int c0 = blockIdx.y * 64;

    __shared__ float Ms[64][33];
    __shared__ float Ws[32][64];

    const int tid = threadIdx.x;
    const int ty = tid >> 4, tx = tid & 15;

    float acc[4][4] = {};

    for (int k0 = 0; k0 < DD; k0 += 32) {
        int hh = k0 >> 5;
        for (int l = tid; l < 512; l += 256) {
            int r = l >> 3, kq = l & 7;
            int m = m0 + r;
            int b_ = m >> 11, n = m & 2047;
            float4 v = *(const float4*)(g_acc + ((size_t)(b_ * HH + hh) * NN + n) * HD + kq * 4);
            Ms[r][kq*4+0] = v.x; Ms[r][kq*4+1] = v.y;
            Ms[r][kq*4+2] = v.z; Ms[r][kq*4+3] = v.w;
        }
        for (int l = tid; l < 512; l += 256) {
            int k = l >> 4, cq = l & 15;
            *(float4*)&Ws[k][cq*4] = *(const float4*)(Wo + (size_t)(k0 + k) * DD + c0 + cq * 4);
        }
        __syncthreads();
        #pragma unroll
        for (int kk = 0; kk < 32; kk++) {
            float a0 = Ms[ty*4+0][kk];
            float a1 = Ms[ty*4+1][kk];
            float a2 = Ms[ty*4+2][kk];
            float a3 = Ms[ty*4+3][kk];
            float4 b = *(float4*)&Ws[kk][tx*4];
            acc[0][0] += a0*b.x; acc[0][1] += a0*b.y; acc[0][2] += a0*b.z; acc[0][3] += a0*b.w;
            acc[1][0] += a1*b.x; acc[1][1] += a1*b.y; acc[1][2] += a1*b.z; acc[1][3] += a1*b.w;
            acc[2][0] += a2*b.x; acc[2][1] += a2*b.y; acc[2][2] += a2*b.z; acc[2][3] += a2*b.w;
            acc[3][0] += a3*b.x; acc[3][1] += a3*b.y; acc[3][2] += a3*b.z; acc[3][3] += a3*b.w;
        }
        __syncthreads();
    }

    #pragma unroll
    for (int i = 0; i < 4; i++) {
        int m = m0 + ty * 4 + i;
        #pragma unroll
        for (int j = 0; j < 4; j++) {
            int cc = c0 + tx * 4 + j;
            out[(size_t)m * DD + cc] = acc[i][j] + bo[cc];
        }
    }
}

// ============================================================
extern "C" void kernel_launch(void* const* d_in, const int* in_sizes, int n_in,
                              void* d_out, int out_size) {
    const float* x      = (const float*)d_in[0];
    const float* Wq     = (const float*)d_in[1];
    const float* bq     = (const float*)d_in[2];
    const float* Wk     = (const float*)d_in[3];
    const float* bk     = (const float*)d_in[4];
    const float* Wv     = (const float*)d_in[5];
    const float* bv     = (const float*)d_in[6];
    const float* Wo     = (const float*)d_in[7];
    const float* bo     = (const float*)d_in[8];
    const float* coeffs = (const float*)d_in[9];
    float* out = (float*)d_out;

    dim3 g1(64, 4, 3);
    qkv_kernel<<<g1, 256>>>(x, Wq, bq, Wk, bk, Wv, bv, coeffs);

    dim3 g2(16, 32);
    attnP_kernel<<<g2, 256>>>();

    pass_kernel<<<g2, 256>>>(coeffs, 1);
    pass_kernel<<<g2, 256>>>(coeffs, 2);
    pass_kernel<<<g2, 256>>>(coeffs, 3);

    dim3 g4(128, 4);
    outproj_kernel<<<g4, 256>>>(Wo, bo, out);
}